// round 1
// baseline (speedup 1.0000x reference)
#include <cuda_runtime.h>

#define NN   50000
#define EE   800000
#define INC  128
#define OUTC 32
#define HH   4
#define EDIM 16
#define HO   128          // H*OUT
#define ENF  (EE + NN)    // edges + self loops = 850000
#define SLOPE 0.2f

// ---------------- scratch (device globals; no allocation allowed) ----------
__device__ float    g_xl[(size_t)NN * HO];       // x @ W_l + b_l   (25.6 MB)
__device__ float    g_xr[(size_t)NN * HO];       // x @ W_r + b_r   (25.6 MB)
__device__ float    g_deg[NN];                   // in-degree
__device__ float    g_asum[(size_t)NN * EDIM];   // scatter-sum of edge attrs
__device__ float    g_score[(size_t)ENF * HH];   // per-edge per-head scores (13.6 MB)
__device__ unsigned g_smax[(size_t)NN * HH];     // segment max (ordered-uint encoding)
__device__ float    g_denom[(size_t)NN * HH];    // softmax denominators
__device__ float4   g_accum[(size_t)NN * OUTC];  // sum ex * x_l[src]  (25.6 MB)

// ---------------- helpers --------------------------------------------------
__device__ __forceinline__ float lrelu(float v) { return v > 0.f ? v : SLOPE * v; }

// monotonic float <-> unsigned encoding for atomicMax
__device__ __forceinline__ unsigned f2u_ord(float f) {
    unsigned u = __float_as_uint(f);
    return (u & 0x80000000u) ? ~u : (u | 0x80000000u);
}
__device__ __forceinline__ float u2f_ord(unsigned u) {
    return (u & 0x80000000u) ? __uint_as_float(u & 0x7fffffffu)
                             : __uint_as_float(~u);
}

__device__ __forceinline__ void red_add_v4(float4* addr, float4 v) {
    asm volatile("red.global.add.v4.f32 [%0], {%1,%2,%3,%4};"
                 :: "l"(addr), "f"(v.x), "f"(v.y), "f"(v.z), "f"(v.w)
                 : "memory");
}

// ---------------- kernel 1: zero scratch -----------------------------------
__global__ void zero_kernel() {
    long i = (long)blockIdx.x * blockDim.x + threadIdx.x;
    long stride = (long)gridDim.x * blockDim.x;
    float* acc = (float*)g_accum;
    for (long j = i; j < (long)NN * HO; j += stride) acc[j] = 0.f;
    for (long j = i; j < (long)NN * HH; j += stride) { g_denom[j] = 0.f; g_smax[j] = 0u; }
    for (long j = i; j < (long)NN; j += stride) g_deg[j] = 0.f;
    for (long j = i; j < (long)NN * EDIM; j += stride) g_asum[j] = 0.f;
}

// ---------------- kernel 2: degree + attr scatter-sum ----------------------
__global__ void deg_attr_kernel(const int* __restrict__ ei,
                                const float* __restrict__ eattr) {
    long tid = (long)blockIdx.x * blockDim.x + threadIdx.x;
    if (tid >= (long)EE * EDIM) return;
    int e = (int)(tid >> 4);
    int d = (int)(tid & 15);
    int t = ei[EE + e];
    atomicAdd(&g_asum[(size_t)t * EDIM + d], eattr[tid]);
    if (d == 0) atomicAdd(&g_deg[t], 1.f);
}

// ---------------- kernel 3: x_l / x_r GEMMs (64-row tile, 256 threads) -----
__global__ void gemm_xlr(const float* __restrict__ x,
                         const float* __restrict__ Wl, const float* __restrict__ bl,
                         const float* __restrict__ Wr, const float* __restrict__ br) {
    __shared__ float xs[64][INC];
    int row0 = blockIdx.x * 64;
    int tid = threadIdx.x;

    const float4* x4 = (const float4*)x;
    for (int i = tid; i < 64 * 32; i += 256) {
        int r = i >> 5, c = i & 31;
        float4 v = make_float4(0.f, 0.f, 0.f, 0.f);
        if (row0 + r < NN) v = x4[(long)(row0 + r) * 32 + c];
        ((float4*)xs[r])[c] = v;
    }
    __syncthreads();

    int tx = tid & 31, ty = tid >> 5;        // tx: 4-col group, ty: row phase
    float4 aL[8], aR[8];
#pragma unroll
    for (int r = 0; r < 8; r++) {
        aL[r] = make_float4(0.f, 0.f, 0.f, 0.f);
        aR[r] = make_float4(0.f, 0.f, 0.f, 0.f);
    }
    const float4* Wl4 = (const float4*)Wl;
    const float4* Wr4 = (const float4*)Wr;
    for (int k = 0; k < INC; k++) {
        float4 wl = Wl4[k * 32 + tx];
        float4 wr = Wr4[k * 32 + tx];
#pragma unroll
        for (int r = 0; r < 8; r++) {
            float xv = xs[ty + r * 8][k];
            aL[r].x = fmaf(xv, wl.x, aL[r].x); aL[r].y = fmaf(xv, wl.y, aL[r].y);
            aL[r].z = fmaf(xv, wl.z, aL[r].z); aL[r].w = fmaf(xv, wl.w, aL[r].w);
            aR[r].x = fmaf(xv, wr.x, aR[r].x); aR[r].y = fmaf(xv, wr.y, aR[r].y);
            aR[r].z = fmaf(xv, wr.z, aR[r].z); aR[r].w = fmaf(xv, wr.w, aR[r].w);
        }
    }
    float4 blv = ((const float4*)bl)[tx];
    float4 brv = ((const float4*)br)[tx];
#pragma unroll
    for (int r = 0; r < 8; r++) {
        int row = row0 + ty + r * 8;
        if (row < NN) {
            float4 ol = make_float4(aL[r].x + blv.x, aL[r].y + blv.y,
                                    aL[r].z + blv.z, aL[r].w + blv.w);
            float4 orr = make_float4(aR[r].x + brv.x, aR[r].y + brv.y,
                                     aR[r].z + brv.z, aR[r].w + brv.w);
            ((float4*)g_xl)[(long)row * 32 + tx] = ol;
            ((float4*)g_xr)[(long)row * 32 + tx] = orr;
        }
    }
}

// ---------------- kernel 4: edge scores + segment max ----------------------
// one warp per edge; lane handles 4 contiguous channels (float4)
__global__ void score_kernel(const int* __restrict__ ei,
                             const float* __restrict__ eattr,
                             const float* __restrict__ We,
                             const float* __restrict__ att) {
    __shared__ float4 sWe[EDIM * 32];   // W_e: 16 x 128 floats
    __shared__ float4 sAtt[32];         // att: 128 floats
    int tid = threadIdx.x;
    for (int i = tid; i < EDIM * 32; i += 256) sWe[i] = ((const float4*)We)[i];
    if (tid < 32) sAtt[tid] = ((const float4*)att)[tid];
    __syncthreads();

    int warp = tid >> 5, lane = tid & 31;
    long ew = (long)blockIdx.x * 8 + warp;
    if (ew >= ENF) return;

    int s, t;
    float a = 0.f;
    if (ew < EE) {
        s = ei[ew];
        t = ei[EE + ew];
        if (lane < EDIM) a = eattr[ew * EDIM + lane];
    } else {
        int n = (int)(ew - EE);
        s = n; t = n;
        if (lane < EDIM) a = g_asum[(size_t)n * EDIM + lane] / fmaxf(g_deg[n], 1.f);
    }

    float4 xl = ((const float4*)g_xl)[(long)s * 32 + lane];
    float4 xr = ((const float4*)g_xr)[(long)t * 32 + lane];
    float4 e = make_float4(0.f, 0.f, 0.f, 0.f);
#pragma unroll
    for (int d = 0; d < EDIM; d++) {
        float ad = __shfl_sync(0xffffffffu, a, d);
        float4 w = sWe[d * 32 + lane];
        e.x = fmaf(ad, w.x, e.x); e.y = fmaf(ad, w.y, e.y);
        e.z = fmaf(ad, w.z, e.z); e.w = fmaf(ad, w.w, e.w);
    }
    float4 m = make_float4(lrelu(xl.x + xr.x + e.x), lrelu(xl.y + xr.y + e.y),
                           lrelu(xl.z + xr.z + e.z), lrelu(xl.w + xr.w + e.w));
    float4 av = sAtt[lane];
    float p = m.x * av.x + m.y * av.y + m.z * av.z + m.w * av.w;
    // reduce over the 8 lanes of each head (32 channels / 4 per lane)
    p += __shfl_xor_sync(0xffffffffu, p, 4);
    p += __shfl_xor_sync(0xffffffffu, p, 2);
    p += __shfl_xor_sync(0xffffffffu, p, 1);
    if ((lane & 7) == 0) {
        int h = lane >> 3;
        g_score[ew * HH + h] = p;
        atomicMax(&g_smax[(size_t)t * HH + h], f2u_ord(p));
    }
}

// ---------------- kernel 5: exp + denom + weighted aggregation -------------
__global__ void aggregate_kernel(const int* __restrict__ ei) {
    int tid = threadIdx.x;
    int warp = tid >> 5, lane = tid & 31;
    long ew = (long)blockIdx.x * 8 + warp;
    if (ew >= ENF) return;

    int s, t;
    if (ew < EE) { s = ei[ew]; t = ei[EE + ew]; }
    else         { s = t = (int)(ew - EE); }

    int h = lane >> 3;
    float sc = g_score[ew * HH + h];
    float mx = u2f_ord(g_smax[(size_t)t * HH + h]);
    float ex = expf(sc - mx);
    if ((lane & 7) == 0) atomicAdd(&g_denom[(size_t)t * HH + h], ex);

    float4 xl = ((const float4*)g_xl)[(long)s * 32 + lane];
    float4 v = make_float4(ex * xl.x, ex * xl.y, ex * xl.z, ex * xl.w);
    red_add_v4(&g_accum[(long)t * 32 + lane], v);
}

// ---------------- kernel 6: finalize (head mean + bias + LeakyReLU) --------
__global__ void finalize_kernel(const float* __restrict__ bias,
                                float* __restrict__ out) {
    int idx = blockIdx.x * blockDim.x + threadIdx.x;
    if (idx >= NN * OUTC) return;
    int n = idx >> 5, c = idx & 31;
    const float* acc = (const float*)g_accum;
    float sum = 0.f;
#pragma unroll
    for (int hh = 0; hh < HH; hh++)
        sum += acc[(size_t)n * HO + hh * OUTC + c] / g_denom[(size_t)n * HH + hh];
    float o = sum * 0.25f + bias[c];
    out[idx] = lrelu(o);
}

// ---------------- launch ---------------------------------------------------
extern "C" void kernel_launch(void* const* d_in, const int* in_sizes, int n_in,
                              void* d_out, int out_size) {
    const float* x     = (const float*)d_in[0];
    const int*   ei    = (const int*)  d_in[1];
    const float* eattr = (const float*)d_in[2];
    const float* Wl    = (const float*)d_in[3];
    const float* bl    = (const float*)d_in[4];
    const float* Wr    = (const float*)d_in[5];
    const float* br    = (const float*)d_in[6];
    const float* We    = (const float*)d_in[7];
    const float* att   = (const float*)d_in[8];
    const float* bias  = (const float*)d_in[9];
    float* out = (float*)d_out;

    zero_kernel<<<4096, 256>>>();
    deg_attr_kernel<<<((long)EE * EDIM + 255) / 256, 256>>>(ei, eattr);
    gemm_xlr<<<(NN + 63) / 64, 256>>>(x, Wl, bl, Wr, br);
    score_kernel<<<(ENF + 7) / 8, 256>>>(ei, eattr, We, att);
    aggregate_kernel<<<(ENF + 7) / 8, 256>>>(ei);
    finalize_kernel<<<(NN * OUTC + 255) / 256, 256>>>(bias, out);
}